// round 8
// baseline (speedup 1.0000x reference)
#include <cuda_runtime.h>
#include <math.h>

#define NCLS   20
#define NBINS  16
#define NANCH  21824
#define BATCH  16
#define MGT    32
#define NGT    (BATCH*MGT)

#define LOSS_BLK   256
#define LOSS_GX    ((NANCH + LOSS_BLK - 1) / LOSS_BLK)   // 86
#define NBLOCKS    (LOSS_GX * BATCH)                      // 1376

// global accumulators (zero-initialized; last block self-resets every run)
__device__ double g_qfl, g_dfl, g_giou;
__device__ int    g_pos;
__device__ unsigned int g_count;

// ---------------------------------------------------------------------------
// Warp-cooperative ATSS threshold for one GT (validated in R7, bit-identical
// to the scalar reference path). The 9 nearest anchors lie in the 5x5 cell
// window per level; 125 candidates across 32 lanes, top-9 by lexicographic
// (dist, idx) via 9 butterfly-argmin rounds, then thr = mean + std(ddof=1).
// ---------------------------------------------------------------------------
__device__ __forceinline__ float atss_threshold(const float4 gt, const int lane) {
    const float gcx = 0.5f * (gt.x + gt.z);
    const float gcy = 0.5f * (gt.y + gt.w);

    float cd[4]; int ci[4];
#pragma unroll
    for (int j = 0; j < 4; j++) {
        const int c = lane + 32 * j;
        float nrm = 3.4e38f; int idx = 0x7fffffff;
        if (c < 125) {
            const int l   = c / 25;
            const int rem = c - 25 * l;
            const int dy  = rem / 5;
            const int dx  = rem - 5 * dy;
            const int   n    = 128 >> l;
            const float s    = (float)(8 << l);
            const int   offs = (65536 - (65536 >> (2 * l))) / 3;
            const int jcx = (int)floorf(gcx / s);
            const int jcy = (int)floorf(gcy / s);
            const int lx0 = min(max(jcx - 2, 0), n - 5);
            const int ly0 = min(max(jcy - 2, 0), n - 5);
            const int ix = lx0 + dx;
            const int iy = ly0 + dy;
            const float cx = (ix + 0.5f) * s;
            const float cy = (iy + 0.5f) * s;
            const float ddx = cx - gcx;
            const float ddy = cy - gcy;
            const float ddy2 = __fmul_rn(ddy, ddy);
            nrm = sqrtf(__fadd_rn(__fmul_rn(ddx, ddx), ddy2));
            idx = offs + iy * n + ix;
        }
        cd[j] = nrm; ci[j] = idx;
    }

    int my_win = 0;
#pragma unroll
    for (int r = 0; r < 9; r++) {
        float bd = cd[0]; int bi = ci[0]; int bs = 0;
#pragma unroll
        for (int k = 1; k < 4; k++) {
            const bool lt = (cd[k] < bd) || (cd[k] == bd && ci[k] < bi);
            if (lt) { bd = cd[k]; bi = ci[k]; bs = k; }
        }
        float wd = bd; int wi = bi;
#pragma unroll
        for (int off = 16; off > 0; off >>= 1) {
            const float od = __shfl_xor_sync(0xffffffffu, wd, off);
            const int   oi = __shfl_xor_sync(0xffffffffu, wi, off);
            if (od < wd || (od == wd && oi < wi)) { wd = od; wi = oi; }
        }
        if (lane == r) my_win = wi;
        if (bi == wi) {
#pragma unroll
            for (int k = 0; k < 4; k++)
                if (k == bs) { cd[k] = 3.4e38f; ci[k] = 0x7fffffff; }
        }
    }

    const float area_g = (gt.z - gt.x) * (gt.w - gt.y);
    float iou = 0.f;
    if (lane < 9) {
        const int idx = my_win;
        const int l = (idx >= 16384) + (idx >= 20480) + (idx >= 21504) + (idx >= 21760);
        const int   n    = 128 >> l;
        const float s    = (float)(8 << l);
        const int   offs = (65536 - (65536 >> (2 * l))) / 3;
        const int r = idx - offs;
        const int iy = r / n, ix = r - iy * n;
        const float cx = (ix + 0.5f) * s, cy = (iy + 0.5f) * s;
        const float half = 2.0f * s;
        const float ax = cx - half, ay = cy - half, az = cx + half, aw = cy + half;
        const float area_a = (az - ax) * (aw - ay);
        const float lx = fmaxf(ax, gt.x), ly = fmaxf(ay, gt.y);
        const float rx = fminf(az, gt.z), ry = fminf(aw, gt.w);
        const float iw = fmaxf(rx - lx, 0.f), ih = fmaxf(ry - ly, 0.f);
        const float inter = iw * ih;
        const float uni = area_a + area_g - inter;
        iou = inter / fmaxf(uni, 1e-9f);
    }

    float v[9];
#pragma unroll
    for (int k = 0; k < 9; k++) v[k] = __shfl_sync(0xffffffffu, iou, k);
    float sum = 0.f;
#pragma unroll
    for (int k = 0; k < 9; k++) sum += v[k];
    const float mean = sum / 9.0f;
    float vs = 0.f;
#pragma unroll
    for (int k = 0; k < 9; k++) { const float t = v[k] - mean; vs += t * t; }
    return mean + sqrtf(vs / 8.0f);
}

// ---------------------------------------------------------------------------
// Single fused kernel: inline per-block thresholds + match + QFL + DFL + GIoU
// + last-block finalization (self-resetting ticket => replay-deterministic).
// ---------------------------------------------------------------------------
__global__ void ldet_kernel(const float* __restrict__ cls_preds,
                            const float* __restrict__ reg_preds,
                            const float4* __restrict__ anchors,
                            const float4* __restrict__ gt_boxes,
                            const int* __restrict__ gt_labels,
                            float* __restrict__ out) {
    __shared__ float4 sGT[MGT];
    __shared__ float  sThr[MGT];
    __shared__ float  sArea[MGT];
    __shared__ int    sLab[MGT];
    const int b    = blockIdx.y;
    const int warp = threadIdx.x >> 5;
    const int lane = threadIdx.x & 31;

    if (threadIdx.x < MGT) {
        const float4 gbx = gt_boxes[b * MGT + threadIdx.x];
        sGT[threadIdx.x]   = gbx;
        sArea[threadIdx.x] = (gbx.z - gbx.x) * (gbx.w - gbx.y);
        sLab[threadIdx.x]  = gt_labels[b * MGT + threadIdx.x];
    }
    // 8 warps x 4 sequential tasks = 32 thresholds (identical in every block)
#pragma unroll
    for (int t = 0; t < 4; t++) {
        const int gl = warp + 8 * t;
        const float4 gtb = __ldg(&gt_boxes[b * MGT + gl]);
        const float thr = atss_threshold(gtb, lane);
        if (lane == 0) sThr[gl] = thr;
    }
    __syncthreads();

    const int n = blockIdx.x * blockDim.x + threadIdx.x;
    float qfl = 0.f, dfl = 0.f, giou_l = 0.f;
    int posi = 0;

    if (n < NANCH) {
        const float4 a = __ldg(&anchors[n]);
        const float aw = a.z - a.x, ah = a.w - a.y;
        const float acx = a.x + 0.5f * aw, acy = a.y + 0.5f * ah;
        const float area_a = aw * ah;

        int matched = -1;
        float m_inter = 0.f, m_uni = 1.f;
#pragma unroll 4
        for (int m = 0; m < MGT; m++) {
            const float4 gbx = sGT[m];
            const float lx = fmaxf(a.x, gbx.x), ly = fmaxf(a.y, gbx.y);
            const float rx = fminf(a.z, gbx.z), ry = fminf(a.w, gbx.w);
            const float iw = fmaxf(rx - lx, 0.f), ih = fmaxf(ry - ly, 0.f);
            const float inter = iw * ih;
            const float uni = area_a + sArea[m] - inter;
            const bool inside = (acx >= gbx.x) && (acx <= gbx.z) &&
                                (acy >= gbx.y) && (acy <= gbx.w);
            if (inside && inter >= sThr[m] * uni) {
                matched = m; m_inter = inter; m_uni = uni;
            }
        }
        const bool pos = matched >= 0;
        posi = pos ? 1 : 0;
        const float it = pos ? (m_inter / fmaxf(m_uni, 1e-9f)) : 0.f;
        const int cls_t = pos ? sLab[matched] : 0;
        const float4 rt = pos ? sGT[matched] : make_float4(0.f, 0.f, 0.f, 0.f);

        // ---- Quality Focal Loss over 20 classes (fast-math) ----
        const float4* cp = (const float4*)(cls_preds + ((size_t)b * NANCH + n) * NCLS);
#pragma unroll
        for (int v = 0; v < 5; v++) {
            const float4 xv = __ldg(&cp[v]);
            const float xs[4] = { xv.x, xv.y, xv.z, xv.w };
#pragma unroll
            for (int j = 0; j < 4; j++) {
                const int c = v * 4 + j;
                const float x = xs[j];
                const bool tpos = (c == cls_t);
                const float e = __expf(-fabsf(x));
                const float sp = __logf(1.0f + e);               // log1p(exp(-|x|))
                const float r = __fdividef(1.0f, 1.0f + e);
                const float psig = (x >= 0.f) ? r : (1.0f - r);  // sigmoid(x)
                const float pt = tpos ? psig : (1.0f - psig);
                const float bce = fmaxf(x, 0.f) - (tpos ? x : 0.f) + sp;
                const float w = fmaf(it, 1.0f - 2.0f * pt, pt);  // it*(1-pt)+(1-it)*pt
                qfl += w * w * bce;
            }
        }

        // ---- DFL + decode + GIoU: positives only ----
        if (pos) {
            const float4* rp = (const float4*)(reg_preds + ((size_t)b * NANCH + n) * 4 * NBINS);
            const float rts[4] = { rt.x, rt.y, rt.z, rt.w };
            float delta[4];
#pragma unroll
            for (int s = 0; s < 4; s++) {
                float l[16];
#pragma unroll
                for (int v = 0; v < 4; v++) {
                    const float4 lv = __ldg(&rp[s * 4 + v]);
                    l[v * 4 + 0] = lv.x; l[v * 4 + 1] = lv.y;
                    l[v * 4 + 2] = lv.z; l[v * 4 + 3] = lv.w;
                }
                float mx = l[0];
#pragma unroll
                for (int k = 1; k < 16; k++) mx = fmaxf(mx, l[k]);

                const float ts = rts[s] * 15.f;
                int li = (int)ts; li = max(0, min(li, 14));
                const int ri = li + 1;
                const float wr = ts - (float)li, wl = 1.f - wr;

                float se = 0.f, ne = 0.f, lli = 0.f, lri = 0.f;
#pragma unroll
                for (int k = 0; k < 16; k++) {
                    const float ek = expf(l[k] - mx);
                    se += ek; ne += ek * (float)k;
                    if (k == li) lli = l[k];
                    if (k == ri) lri = l[k];
                }
                const float lz = mx + logf(se);
                dfl += -(wl * (lli - lz) + wr * (lri - lz));
                delta[s] = ne / (se * 15.f);
            }
            const float pcx = delta[0] * aw + acx;
            const float pcy = delta[1] * ah + acy;
            const float pw = expf(delta[2]) * aw;
            const float ph = expf(delta[3]) * ah;
            const float px1 = pcx - 0.5f * pw, py1 = pcy - 0.5f * ph;
            const float px2 = pcx + 0.5f * pw, py2 = pcy + 0.5f * ph;
            const float lx = fmaxf(px1, rt.x), ly = fmaxf(py1, rt.y);
            const float rx = fminf(px2, rt.z), ry = fminf(py2, rt.w);
            const float iw = fmaxf(rx - lx, 0.f), ih = fmaxf(ry - ly, 0.f);
            const float inter = iw * ih;
            const float pa = (px2 - px1) * (py2 - py1);
            const float ga = (rt.z - rt.x) * (rt.w - rt.y);
            const float uni = pa + ga - inter;
            const float iou = inter / fmaxf(uni, 1e-9f);
            const float ex1 = fminf(px1, rt.x), ey1 = fminf(py1, rt.y);
            const float ex2 = fmaxf(px2, rt.z), ey2 = fmaxf(py2, rt.w);
            const float ew = fmaxf(ex2 - ex1, 0.f), eh = fmaxf(ey2 - ey1, 0.f);
            const float enc = ew * eh;
            const float gv = iou - (enc - uni) / fmaxf(enc, 1e-9f);
            giou_l = 1.f - gv;
        }
    }

    // ---- reduction: warp -> block -> global double atomics ----
#pragma unroll
    for (int off = 16; off > 0; off >>= 1) {
        qfl    += __shfl_xor_sync(0xffffffffu, qfl,    off);
        dfl    += __shfl_xor_sync(0xffffffffu, dfl,    off);
        giou_l += __shfl_xor_sync(0xffffffffu, giou_l, off);
        posi   += __shfl_xor_sync(0xffffffffu, posi,   off);
    }
    __shared__ float rq[8], rd[8], rg[8];
    __shared__ int   rp_[8];
    if (lane == 0) { rq[warp] = qfl; rd[warp] = dfl; rg[warp] = giou_l; rp_[warp] = posi; }
    __syncthreads();
    if (threadIdx.x == 0) {
        float q = 0.f, dd = 0.f, gg = 0.f; int pp = 0;
#pragma unroll
        for (int wi = 0; wi < LOSS_BLK / 32; wi++) {
            q += rq[wi]; dd += rd[wi]; gg += rg[wi]; pp += rp_[wi];
        }
        if (q  != 0.f) atomicAdd(&g_qfl,  (double)q);
        if (dd != 0.f) atomicAdd(&g_dfl,  (double)dd);
        if (gg != 0.f) atomicAdd(&g_giou, (double)gg);
        if (pp != 0)   atomicAdd(&g_pos,  pp);
        __threadfence();
        const unsigned int ticket = atomicAdd(&g_count, 1u);
        if (ticket == NBLOCKS - 1) {
            const int pos = *((volatile int*)&g_pos);
            const double sq = *((volatile double*)&g_qfl);
            const double sd = *((volatile double*)&g_dfl);
            const double sg = *((volatile double*)&g_giou);
            const double npc = (double)max(pos, 1);
            const double qv = sq / npc;
            double df = sd / (double)max(4 * pos, 1);
            df = fmin(fmax(df, 0.0), 1.0);
            const double gi = sg / npc;
            out[0] = (float)(qv + df + gi);
            out[1] = (float)qv;
            out[2] = (float)df;
            out[3] = (float)gi;
            // reset globals so every run (and graph replay) starts clean
            g_qfl = 0.0; g_dfl = 0.0; g_giou = 0.0; g_pos = 0;
            __threadfence();
            g_count = 0u;
        }
    }
}

extern "C" void kernel_launch(void* const* d_in, const int* in_sizes, int n_in,
                              void* d_out, int out_size) {
    const float*  cls_preds = (const float*)d_in[0];
    const float*  reg_preds = (const float*)d_in[1];
    const float4* anchors   = (const float4*)d_in[2];
    const float4* gt_boxes  = (const float4*)d_in[3];
    const int*    gt_labels = (const int*)d_in[4];
    float* out = (float*)d_out;

    dim3 grid(LOSS_GX, BATCH);
    ldet_kernel<<<grid, LOSS_BLK>>>(cls_preds, reg_preds, anchors, gt_boxes, gt_labels, out);
}

// round 9
// speedup vs baseline: 2.6349x; 2.6349x over previous
#include <cuda_runtime.h>
#include <math.h>

#define NCLS   20
#define NBINS  16
#define NANCH  21824
#define BATCH  16
#define MGT    32
#define NGT    (BATCH*MGT)

#define LOSS_BLK   256
#define LOSS_GX    ((NANCH + LOSS_BLK - 1) / LOSS_BLK)   // 86
#define NBLOCKS    (LOSS_GX * BATCH)                      // 1376

// global accumulators / scratch (no device mallocs allowed)
__device__ double g_qfl, g_dfl, g_giou;
__device__ int    g_pos;
__device__ unsigned int g_count;   // zero-init; last block self-resets
__device__ float  g_thr[NGT];

// ---------------------------------------------------------------------------
// Phase A: ATSS threshold, one WARP per GT (R7-validated, 7.5us).
// 125 analytic grid candidates across 32 lanes; top-9 by lexicographic
// (dist, idx) via 9 butterfly-argmin rounds; thr = mean + std(ddof=1)
// evaluated in the validated sequential order (bit-identical thresholds).
// Also zeroes the global accumulators.
// ---------------------------------------------------------------------------
__global__ void thr_kernel(const float4* __restrict__ gt_boxes) {
    const int warp = threadIdx.x >> 5;
    const int lane = threadIdx.x & 31;
    const int g = blockIdx.x * 8 + warp;            // 0..511
    if (blockIdx.x == 0 && threadIdx.x == 0) {
        g_qfl = 0.0; g_dfl = 0.0; g_giou = 0.0; g_pos = 0;
    }
    if (g >= NGT) return;

    const float4 gt = __ldg(&gt_boxes[g]);
    const float gcx = 0.5f * (gt.x + gt.z);
    const float gcy = 0.5f * (gt.y + gt.w);

    float cd[4]; int ci[4];
#pragma unroll
    for (int j = 0; j < 4; j++) {
        const int c = lane + 32 * j;
        float nrm = 3.4e38f; int idx = 0x7fffffff;
        if (c < 125) {
            const int l   = c / 25;
            const int rem = c - 25 * l;
            const int dy  = rem / 5;
            const int dx  = rem - 5 * dy;
            const int   n    = 128 >> l;
            const float s    = (float)(8 << l);
            const int   offs = (65536 - (65536 >> (2 * l))) / 3;
            const int jcx = (int)floorf(gcx / s);
            const int jcy = (int)floorf(gcy / s);
            const int lx0 = min(max(jcx - 2, 0), n - 5);
            const int ly0 = min(max(jcy - 2, 0), n - 5);
            const int ix = lx0 + dx;
            const int iy = ly0 + dy;
            const float cx = (ix + 0.5f) * s;
            const float cy = (iy + 0.5f) * s;
            const float ddx = cx - gcx;
            const float ddy = cy - gcy;
            const float ddy2 = __fmul_rn(ddy, ddy);
            nrm = sqrtf(__fadd_rn(__fmul_rn(ddx, ddx), ddy2));
            idx = offs + iy * n + ix;
        }
        cd[j] = nrm; ci[j] = idx;
    }

    int my_win = 0;
#pragma unroll
    for (int r = 0; r < 9; r++) {
        float bd = cd[0]; int bi = ci[0]; int bs = 0;
#pragma unroll
        for (int k = 1; k < 4; k++) {
            const bool lt = (cd[k] < bd) || (cd[k] == bd && ci[k] < bi);
            if (lt) { bd = cd[k]; bi = ci[k]; bs = k; }
        }
        float wd = bd; int wi = bi;
#pragma unroll
        for (int off = 16; off > 0; off >>= 1) {
            const float od = __shfl_xor_sync(0xffffffffu, wd, off);
            const int   oi = __shfl_xor_sync(0xffffffffu, wi, off);
            if (od < wd || (od == wd && oi < wi)) { wd = od; wi = oi; }
        }
        if (lane == r) my_win = wi;
        if (bi == wi) {
#pragma unroll
            for (int k = 0; k < 4; k++)
                if (k == bs) { cd[k] = 3.4e38f; ci[k] = 0x7fffffff; }
        }
    }

    const float area_g = (gt.z - gt.x) * (gt.w - gt.y);
    float iou = 0.f;
    if (lane < 9) {
        const int idx = my_win;
        const int l = (idx >= 16384) + (idx >= 20480) + (idx >= 21504) + (idx >= 21760);
        const int   n    = 128 >> l;
        const float s    = (float)(8 << l);
        const int   offs = (65536 - (65536 >> (2 * l))) / 3;
        const int r = idx - offs;
        const int iy = r / n, ix = r - iy * n;
        const float cx = (ix + 0.5f) * s, cy = (iy + 0.5f) * s;
        const float half = 2.0f * s;
        const float ax = cx - half, ay = cy - half, az = cx + half, aw = cy + half;
        const float area_a = (az - ax) * (aw - ay);
        const float lx = fmaxf(ax, gt.x), ly = fmaxf(ay, gt.y);
        const float rx = fminf(az, gt.z), ry = fminf(aw, gt.w);
        const float iw = fmaxf(rx - lx, 0.f), ih = fmaxf(ry - ly, 0.f);
        const float inter = iw * ih;
        const float uni = area_a + area_g - inter;
        iou = inter / fmaxf(uni, 1e-9f);
    }

    float v[9];
#pragma unroll
    for (int k = 0; k < 9; k++) v[k] = __shfl_sync(0xffffffffu, iou, k);
    if (lane == 0) {
        float sum = 0.f;
#pragma unroll
        for (int k = 0; k < 9; k++) sum += v[k];
        const float mean = sum / 9.0f;
        float vs = 0.f;
#pragma unroll
        for (int k = 0; k < 9; k++) { const float t = v[k] - mean; vs += t * t; }
        g_thr[g] = mean + sqrtf(vs / 8.0f);
    }
}

// ---------------------------------------------------------------------------
// Phase B: fused match + QFL + DFL + GIoU + last-block finalization.
// One thread per (b, n); divide-free match; fast-math QFL; positives-only
// reg path; ticket-based finalize (R8-validated) replaces final_kernel.
// ---------------------------------------------------------------------------
__global__ void loss_kernel(const float* __restrict__ cls_preds,
                            const float* __restrict__ reg_preds,
                            const float4* __restrict__ anchors,
                            const float4* __restrict__ gt_boxes,
                            const int* __restrict__ gt_labels,
                            float* __restrict__ out) {
    __shared__ float4 sGT[MGT];
    __shared__ float  sThr[MGT];
    __shared__ float  sArea[MGT];
    __shared__ int    sLab[MGT];
    const int b = blockIdx.y;
    if (threadIdx.x < MGT) {
        const float4 gbx = gt_boxes[b * MGT + threadIdx.x];
        sGT[threadIdx.x]   = gbx;
        sArea[threadIdx.x] = (gbx.z - gbx.x) * (gbx.w - gbx.y);
        sThr[threadIdx.x]  = g_thr[b * MGT + threadIdx.x];
        sLab[threadIdx.x]  = gt_labels[b * MGT + threadIdx.x];
    }
    __syncthreads();

    const int n = blockIdx.x * blockDim.x + threadIdx.x;
    float qfl = 0.f, dfl = 0.f, giou_l = 0.f;
    int posi = 0;

    if (n < NANCH) {
        const float4 a = __ldg(&anchors[n]);
        const float aw = a.z - a.x, ah = a.w - a.y;
        const float acx = a.x + 0.5f * aw, acy = a.y + 0.5f * ah;
        const float area_a = aw * ah;

        int matched = -1;
        float m_inter = 0.f, m_uni = 1.f;
#pragma unroll 4
        for (int m = 0; m < MGT; m++) {
            const float4 gbx = sGT[m];
            const float lx = fmaxf(a.x, gbx.x), ly = fmaxf(a.y, gbx.y);
            const float rx = fminf(a.z, gbx.z), ry = fminf(a.w, gbx.w);
            const float iw = fmaxf(rx - lx, 0.f), ih = fmaxf(ry - ly, 0.f);
            const float inter = iw * ih;
            const float uni = area_a + sArea[m] - inter;
            const bool inside = (acx >= gbx.x) && (acx <= gbx.z) &&
                                (acy >= gbx.y) && (acy <= gbx.w);
            if (inside && inter >= sThr[m] * uni) {
                matched = m; m_inter = inter; m_uni = uni;
            }
        }
        const bool pos = matched >= 0;
        posi = pos ? 1 : 0;
        const float it = pos ? (m_inter / fmaxf(m_uni, 1e-9f)) : 0.f;
        const int cls_t = pos ? sLab[matched] : 0;
        const float4 rt = pos ? sGT[matched] : make_float4(0.f, 0.f, 0.f, 0.f);

        // ---- Quality Focal Loss over 20 classes (fast-math) ----
        const float4* cp = (const float4*)(cls_preds + ((size_t)b * NANCH + n) * NCLS);
#pragma unroll
        for (int v = 0; v < 5; v++) {
            const float4 xv = __ldg(&cp[v]);
            const float xs[4] = { xv.x, xv.y, xv.z, xv.w };
#pragma unroll
            for (int j = 0; j < 4; j++) {
                const int c = v * 4 + j;
                const float x = xs[j];
                const bool tpos = (c == cls_t);
                const float e = __expf(-fabsf(x));
                const float sp = __logf(1.0f + e);               // log1p(exp(-|x|))
                const float r = __fdividef(1.0f, 1.0f + e);
                const float psig = (x >= 0.f) ? r : (1.0f - r);  // sigmoid(x)
                const float pt = tpos ? psig : (1.0f - psig);
                const float bce = fmaxf(x, 0.f) - (tpos ? x : 0.f) + sp;
                const float w = fmaf(it, 1.0f - 2.0f * pt, pt);  // it*(1-pt)+(1-it)*pt
                qfl += w * w * bce;
            }
        }

        // ---- DFL + decode + GIoU: positives only ----
        if (pos) {
            const float4* rp = (const float4*)(reg_preds + ((size_t)b * NANCH + n) * 4 * NBINS);
            const float rts[4] = { rt.x, rt.y, rt.z, rt.w };
            float delta[4];
#pragma unroll
            for (int s = 0; s < 4; s++) {
                float l[16];
#pragma unroll
                for (int v = 0; v < 4; v++) {
                    const float4 lv = __ldg(&rp[s * 4 + v]);
                    l[v * 4 + 0] = lv.x; l[v * 4 + 1] = lv.y;
                    l[v * 4 + 2] = lv.z; l[v * 4 + 3] = lv.w;
                }
                float mx = l[0];
#pragma unroll
                for (int k = 1; k < 16; k++) mx = fmaxf(mx, l[k]);

                const float ts = rts[s] * 15.f;
                int li = (int)ts; li = max(0, min(li, 14));
                const int ri = li + 1;
                const float wr = ts - (float)li, wl = 1.f - wr;

                float se = 0.f, ne = 0.f, lli = 0.f, lri = 0.f;
#pragma unroll
                for (int k = 0; k < 16; k++) {
                    const float ek = expf(l[k] - mx);
                    se += ek; ne += ek * (float)k;
                    if (k == li) lli = l[k];
                    if (k == ri) lri = l[k];
                }
                const float lz = mx + logf(se);
                dfl += -(wl * (lli - lz) + wr * (lri - lz));
                delta[s] = ne / (se * 15.f);
            }
            const float pcx = delta[0] * aw + acx;
            const float pcy = delta[1] * ah + acy;
            const float pw = expf(delta[2]) * aw;
            const float ph = expf(delta[3]) * ah;
            const float px1 = pcx - 0.5f * pw, py1 = pcy - 0.5f * ph;
            const float px2 = pcx + 0.5f * pw, py2 = pcy + 0.5f * ph;
            const float lx = fmaxf(px1, rt.x), ly = fmaxf(py1, rt.y);
            const float rx = fminf(px2, rt.z), ry = fminf(py2, rt.w);
            const float iw = fmaxf(rx - lx, 0.f), ih = fmaxf(ry - ly, 0.f);
            const float inter = iw * ih;
            const float pa = (px2 - px1) * (py2 - py1);
            const float ga = (rt.z - rt.x) * (rt.w - rt.y);
            const float uni = pa + ga - inter;
            const float iou = inter / fmaxf(uni, 1e-9f);
            const float ex1 = fminf(px1, rt.x), ey1 = fminf(py1, rt.y);
            const float ex2 = fmaxf(px2, rt.z), ey2 = fmaxf(py2, rt.w);
            const float ew = fmaxf(ex2 - ex1, 0.f), eh = fmaxf(ey2 - ey1, 0.f);
            const float enc = ew * eh;
            const float gv = iou - (enc - uni) / fmaxf(enc, 1e-9f);
            giou_l = 1.f - gv;
        }
    }

    // ---- reduction: warp -> block -> global double atomics ----
#pragma unroll
    for (int off = 16; off > 0; off >>= 1) {
        qfl    += __shfl_xor_sync(0xffffffffu, qfl,    off);
        dfl    += __shfl_xor_sync(0xffffffffu, dfl,    off);
        giou_l += __shfl_xor_sync(0xffffffffu, giou_l, off);
        posi   += __shfl_xor_sync(0xffffffffu, posi,   off);
    }
    __shared__ float rq[8], rd[8], rg[8];
    __shared__ int   rp_[8];
    const int warp = threadIdx.x >> 5;
    const int lane = threadIdx.x & 31;
    if (lane == 0) { rq[warp] = qfl; rd[warp] = dfl; rg[warp] = giou_l; rp_[warp] = posi; }
    __syncthreads();
    if (threadIdx.x == 0) {
        float q = 0.f, dd = 0.f, gg = 0.f; int pp = 0;
#pragma unroll
        for (int wi = 0; wi < LOSS_BLK / 32; wi++) {
            q += rq[wi]; dd += rd[wi]; gg += rg[wi]; pp += rp_[wi];
        }
        if (q  != 0.f) atomicAdd(&g_qfl,  (double)q);
        if (dd != 0.f) atomicAdd(&g_dfl,  (double)dd);
        if (gg != 0.f) atomicAdd(&g_giou, (double)gg);
        if (pp != 0)   atomicAdd(&g_pos,  pp);
        __threadfence();
        const unsigned int ticket = atomicAdd(&g_count, 1u);
        if (ticket == NBLOCKS - 1) {
            const int pos = *((volatile int*)&g_pos);
            const double sq = *((volatile double*)&g_qfl);
            const double sd = *((volatile double*)&g_dfl);
            const double sg = *((volatile double*)&g_giou);
            const double npc = (double)max(pos, 1);
            const double qv = sq / npc;
            double df = sd / (double)max(4 * pos, 1);
            df = fmin(fmax(df, 0.0), 1.0);
            const double gi = sg / npc;
            out[0] = (float)(qv + df + gi);
            out[1] = (float)qv;
            out[2] = (float)df;
            out[3] = (float)gi;
            // leave globals clean for the next run / graph replay
            g_qfl = 0.0; g_dfl = 0.0; g_giou = 0.0; g_pos = 0;
            __threadfence();
            g_count = 0u;
        }
    }
}

extern "C" void kernel_launch(void* const* d_in, const int* in_sizes, int n_in,
                              void* d_out, int out_size) {
    const float*  cls_preds = (const float*)d_in[0];
    const float*  reg_preds = (const float*)d_in[1];
    const float4* anchors   = (const float4*)d_in[2];
    const float4* gt_boxes  = (const float4*)d_in[3];
    const int*    gt_labels = (const int*)d_in[4];
    float* out = (float*)d_out;

    thr_kernel<<<64, 256>>>(gt_boxes);
    dim3 grid(LOSS_GX, BATCH);
    loss_kernel<<<grid, LOSS_BLK>>>(cls_preds, reg_preds, anchors, gt_boxes, gt_labels, out);
}

// round 10
// speedup vs baseline: 3.0000x; 1.1385x over previous
#include <cuda_runtime.h>
#include <math.h>

#define NCLS   20
#define NBINS  16
#define NANCH  21824
#define BATCH  16
#define MGT    32
#define NGT    (BATCH*MGT)

#define LOSS_BLK   256
#define LOSS_GX    ((NANCH + LOSS_BLK - 1) / LOSS_BLK)   // 86
#define NBLOCKS    (LOSS_GX * BATCH)                      // 1376

// global accumulators / scratch (no device mallocs allowed)
__device__ double g_qfl, g_dfl, g_giou;
__device__ int    g_pos;
__device__ unsigned int g_count;                 // ticket; self-resetting
__device__ int    g_matched[BATCH * NANCH];      // 0 = none, else m+1; self-clearing

// ---------------------------------------------------------------------------
// Warp-cooperative ATSS threshold for one GT (R7-validated, bit-identical).
// Returns the threshold on ALL lanes (each lane redundantly reduces the
// broadcast v[0..8] in the validated sequential order).
// ---------------------------------------------------------------------------
__device__ __forceinline__ float atss_threshold(const float4 gt, const int lane) {
    const float gcx = 0.5f * (gt.x + gt.z);
    const float gcy = 0.5f * (gt.y + gt.w);

    float cd[4]; int ci[4];
#pragma unroll
    for (int j = 0; j < 4; j++) {
        const int c = lane + 32 * j;
        float nrm = 3.4e38f; int idx = 0x7fffffff;
        if (c < 125) {
            const int l   = c / 25;
            const int rem = c - 25 * l;
            const int dy  = rem / 5;
            const int dx  = rem - 5 * dy;
            const int   n    = 128 >> l;
            const float s    = (float)(8 << l);
            const int   offs = (65536 - (65536 >> (2 * l))) / 3;
            const int jcx = (int)floorf(gcx / s);
            const int jcy = (int)floorf(gcy / s);
            const int lx0 = min(max(jcx - 2, 0), n - 5);
            const int ly0 = min(max(jcy - 2, 0), n - 5);
            const int ix = lx0 + dx;
            const int iy = ly0 + dy;
            const float cx = (ix + 0.5f) * s;
            const float cy = (iy + 0.5f) * s;
            const float ddx = cx - gcx;
            const float ddy = cy - gcy;
            const float ddy2 = __fmul_rn(ddy, ddy);
            nrm = sqrtf(__fadd_rn(__fmul_rn(ddx, ddx), ddy2));
            idx = offs + iy * n + ix;
        }
        cd[j] = nrm; ci[j] = idx;
    }

    int my_win = 0;
#pragma unroll
    for (int r = 0; r < 9; r++) {
        float bd = cd[0]; int bi = ci[0]; int bs = 0;
#pragma unroll
        for (int k = 1; k < 4; k++) {
            const bool lt = (cd[k] < bd) || (cd[k] == bd && ci[k] < bi);
            if (lt) { bd = cd[k]; bi = ci[k]; bs = k; }
        }
        float wd = bd; int wi = bi;
#pragma unroll
        for (int off = 16; off > 0; off >>= 1) {
            const float od = __shfl_xor_sync(0xffffffffu, wd, off);
            const int   oi = __shfl_xor_sync(0xffffffffu, wi, off);
            if (od < wd || (od == wd && oi < wi)) { wd = od; wi = oi; }
        }
        if (lane == r) my_win = wi;
        if (bi == wi) {
#pragma unroll
            for (int k = 0; k < 4; k++)
                if (k == bs) { cd[k] = 3.4e38f; ci[k] = 0x7fffffff; }
        }
    }

    const float area_g = (gt.z - gt.x) * (gt.w - gt.y);
    float iou = 0.f;
    if (lane < 9) {
        const int idx = my_win;
        const int l = (idx >= 16384) + (idx >= 20480) + (idx >= 21504) + (idx >= 21760);
        const int   n    = 128 >> l;
        const float s    = (float)(8 << l);
        const int   offs = (65536 - (65536 >> (2 * l))) / 3;
        const int r = idx - offs;
        const int iy = r / n, ix = r - iy * n;
        const float cx = (ix + 0.5f) * s, cy = (iy + 0.5f) * s;
        const float half = 2.0f * s;
        const float ax = cx - half, ay = cy - half, az = cx + half, aw = cy + half;
        const float area_a = (az - ax) * (aw - ay);
        const float lx = fmaxf(ax, gt.x), ly = fmaxf(ay, gt.y);
        const float rx = fminf(az, gt.z), ry = fminf(aw, gt.w);
        const float iw = fmaxf(rx - lx, 0.f), ih = fmaxf(ry - ly, 0.f);
        const float inter = iw * ih;
        const float uni = area_a + area_g - inter;
        iou = inter / fmaxf(uni, 1e-9f);
    }

    float v[9];
#pragma unroll
    for (int k = 0; k < 9; k++) v[k] = __shfl_sync(0xffffffffu, iou, k);
    float sum = 0.f;
#pragma unroll
    for (int k = 0; k < 9; k++) sum += v[k];
    const float mean = sum / 9.0f;
    float vs = 0.f;
#pragma unroll
    for (int k = 0; k < 9; k++) { const float t = v[k] - mean; vs += t * t; }
    return mean + sqrtf(vs / 8.0f);
}

// ---------------------------------------------------------------------------
// Phase A: one WARP per GT. Compute threshold, then SCATTER matches: only
// anchors whose centers lie inside the GT box can match; enumerate them via
// analytic per-level index ranges (padded, then re-tested with the exact
// float compares), apply the validated IoU condition, atomicMax(m+1)
// ("largest GT index wins" == reference last-wins semantics).
// ---------------------------------------------------------------------------
__global__ void match_kernel(const float4* __restrict__ gt_boxes) {
    const int warp = threadIdx.x >> 5;
    const int lane = threadIdx.x & 31;
    const int g = blockIdx.x * 4 + warp;            // 0..511 (128 blocks x 4 warps)
    if (blockIdx.x == 0 && threadIdx.x == 0) {
        g_qfl = 0.0; g_dfl = 0.0; g_giou = 0.0; g_pos = 0;   // defensive (finalize also resets)
    }
    if (g >= NGT) return;

    const float4 gt = __ldg(&gt_boxes[g]);
    const float thr = atss_threshold(gt, lane);

    const int b = g >> 5;
    const int m = g & 31;
    int* mslice = g_matched + b * NANCH;
    const float area_g = (gt.z - gt.x) * (gt.w - gt.y);

#pragma unroll
    for (int l = 0; l < 5; l++) {
        const int   n    = 128 >> l;
        const float s    = (float)(8 << l);
        const float half = 2.0f * s;
        const int   offs = (65536 - (65536 >> (2 * l))) / 3;
        const int ix0 = max(0,     (int)floorf(gt.x / s - 0.5f) - 1);
        const int ix1 = min(n - 1, (int)ceilf (gt.z / s - 0.5f) + 1);
        const int iy0 = max(0,     (int)floorf(gt.y / s - 0.5f) - 1);
        const int iy1 = min(n - 1, (int)ceilf (gt.w / s - 0.5f) + 1);
        const int W = ix1 - ix0 + 1;
        const int H = iy1 - iy0 + 1;
        const int tot = W * H;
        for (int t = lane; t < tot; t += 32) {
            const int ty = t / W;
            const int iy = iy0 + ty;
            const int ix = ix0 + (t - ty * W);
            const float cx = (ix + 0.5f) * s;
            const float cy = (iy + 0.5f) * s;
            const bool inside = (cx >= gt.x) && (cx <= gt.z) &&
                                (cy >= gt.y) && (cy <= gt.w);
            if (inside) {
                const float ax = cx - half, ay = cy - half;
                const float az = cx + half, aw = cy + half;
                const float area_a = (az - ax) * (aw - ay);
                const float lx = fmaxf(ax, gt.x), ly = fmaxf(ay, gt.y);
                const float rx = fminf(az, gt.z), ry = fminf(aw, gt.w);
                const float iw = fmaxf(rx - lx, 0.f), ih = fmaxf(ry - ly, 0.f);
                const float inter = iw * ih;
                const float uni = area_a + area_g - inter;
                if (inter >= thr * uni)
                    atomicMax(&mslice[offs + iy * n + ix], m + 1);
            }
        }
    }
}

// ---------------------------------------------------------------------------
// Phase B: loss. One thread per (b, n). No 32-GT loop: read matched[] (and
// self-clear it), recompute the single matched IoU with the validated
// arithmetic, then QFL (fast-math), positives-only DFL/GIoU, ticket finalize.
// ---------------------------------------------------------------------------
__global__ void loss_kernel(const float* __restrict__ cls_preds,
                            const float* __restrict__ reg_preds,
                            const float4* __restrict__ anchors,
                            const float4* __restrict__ gt_boxes,
                            const int* __restrict__ gt_labels,
                            float* __restrict__ out) {
    __shared__ float4 sGT[MGT];
    __shared__ float  sArea[MGT];
    __shared__ int    sLab[MGT];
    const int b = blockIdx.y;
    if (threadIdx.x < MGT) {
        const float4 gbx = gt_boxes[b * MGT + threadIdx.x];
        sGT[threadIdx.x]   = gbx;
        sArea[threadIdx.x] = (gbx.z - gbx.x) * (gbx.w - gbx.y);
        sLab[threadIdx.x]  = gt_labels[b * MGT + threadIdx.x];
    }
    __syncthreads();

    const int n = blockIdx.x * blockDim.x + threadIdx.x;
    float qfl = 0.f, dfl = 0.f, giou_l = 0.f;
    int posi = 0;

    if (n < NANCH) {
        const size_t midx = (size_t)b * NANCH + n;
        const int mm = g_matched[midx];
        const bool pos = mm > 0;
        if (pos) g_matched[midx] = 0;              // self-clean for next run
        const int matched = pos ? (mm - 1) : 0;

        const float4 a = __ldg(&anchors[n]);
        const float aw = a.z - a.x, ah = a.w - a.y;
        const float acx = a.x + 0.5f * aw, acy = a.y + 0.5f * ah;

        float it = 0.f;
        if (pos) {
            const float area_a = aw * ah;
            const float4 gbx = sGT[matched];
            const float lx = fmaxf(a.x, gbx.x), ly = fmaxf(a.y, gbx.y);
            const float rx = fminf(a.z, gbx.z), ry = fminf(a.w, gbx.w);
            const float iw = fmaxf(rx - lx, 0.f), ih = fmaxf(ry - ly, 0.f);
            const float inter = iw * ih;
            const float uni = area_a + sArea[matched] - inter;
            it = inter / fmaxf(uni, 1e-9f);
        }
        posi = pos ? 1 : 0;
        const int cls_t = pos ? sLab[matched] : 0;
        const float4 rt = pos ? sGT[matched] : make_float4(0.f, 0.f, 0.f, 0.f);

        // ---- Quality Focal Loss over 20 classes (fast-math) ----
        const float4* cp = (const float4*)(cls_preds + ((size_t)b * NANCH + n) * NCLS);
#pragma unroll
        for (int v = 0; v < 5; v++) {
            const float4 xv = __ldg(&cp[v]);
            const float xs[4] = { xv.x, xv.y, xv.z, xv.w };
#pragma unroll
            for (int j = 0; j < 4; j++) {
                const int c = v * 4 + j;
                const float x = xs[j];
                const bool tpos = (c == cls_t);
                const float e = __expf(-fabsf(x));
                const float sp = __logf(1.0f + e);               // log1p(exp(-|x|))
                const float r = __fdividef(1.0f, 1.0f + e);
                const float psig = (x >= 0.f) ? r : (1.0f - r);  // sigmoid(x)
                const float pt = tpos ? psig : (1.0f - psig);
                const float bce = fmaxf(x, 0.f) - (tpos ? x : 0.f) + sp;
                const float w = fmaf(it, 1.0f - 2.0f * pt, pt);  // it*(1-pt)+(1-it)*pt
                qfl += w * w * bce;
            }
        }

        // ---- DFL + decode + GIoU: positives only ----
        if (pos) {
            const float4* rp = (const float4*)(reg_preds + ((size_t)b * NANCH + n) * 4 * NBINS);
            const float rts[4] = { rt.x, rt.y, rt.z, rt.w };
            float delta[4];
#pragma unroll
            for (int s = 0; s < 4; s++) {
                float l[16];
#pragma unroll
                for (int v = 0; v < 4; v++) {
                    const float4 lv = __ldg(&rp[s * 4 + v]);
                    l[v * 4 + 0] = lv.x; l[v * 4 + 1] = lv.y;
                    l[v * 4 + 2] = lv.z; l[v * 4 + 3] = lv.w;
                }
                float mx = l[0];
#pragma unroll
                for (int k = 1; k < 16; k++) mx = fmaxf(mx, l[k]);

                const float ts = rts[s] * 15.f;
                int li = (int)ts; li = max(0, min(li, 14));
                const int ri = li + 1;
                const float wr = ts - (float)li, wl = 1.f - wr;

                float se = 0.f, ne = 0.f, lli = 0.f, lri = 0.f;
#pragma unroll
                for (int k = 0; k < 16; k++) {
                    const float ek = expf(l[k] - mx);
                    se += ek; ne += ek * (float)k;
                    if (k == li) lli = l[k];
                    if (k == ri) lri = l[k];
                }
                const float lz = mx + logf(se);
                dfl += -(wl * (lli - lz) + wr * (lri - lz));
                delta[s] = ne / (se * 15.f);
            }
            const float pcx = delta[0] * aw + acx;
            const float pcy = delta[1] * ah + acy;
            const float pw = expf(delta[2]) * aw;
            const float ph = expf(delta[3]) * ah;
            const float px1 = pcx - 0.5f * pw, py1 = pcy - 0.5f * ph;
            const float px2 = pcx + 0.5f * pw, py2 = pcy + 0.5f * ph;
            const float lx = fmaxf(px1, rt.x), ly = fmaxf(py1, rt.y);
            const float rx = fminf(px2, rt.z), ry = fminf(py2, rt.w);
            const float iw = fmaxf(rx - lx, 0.f), ih = fmaxf(ry - ly, 0.f);
            const float inter = iw * ih;
            const float pa = (px2 - px1) * (py2 - py1);
            const float ga = (rt.z - rt.x) * (rt.w - rt.y);
            const float uni = pa + ga - inter;
            const float iou = inter / fmaxf(uni, 1e-9f);
            const float ex1 = fminf(px1, rt.x), ey1 = fminf(py1, rt.y);
            const float ex2 = fmaxf(px2, rt.z), ey2 = fmaxf(py2, rt.w);
            const float ew = fmaxf(ex2 - ex1, 0.f), eh = fmaxf(ey2 - ey1, 0.f);
            const float enc = ew * eh;
            const float gv = iou - (enc - uni) / fmaxf(enc, 1e-9f);
            giou_l = 1.f - gv;
        }
    }

    // ---- reduction: warp -> block -> global double atomics ----
#pragma unroll
    for (int off = 16; off > 0; off >>= 1) {
        qfl    += __shfl_xor_sync(0xffffffffu, qfl,    off);
        dfl    += __shfl_xor_sync(0xffffffffu, dfl,    off);
        giou_l += __shfl_xor_sync(0xffffffffu, giou_l, off);
        posi   += __shfl_xor_sync(0xffffffffu, posi,   off);
    }
    __shared__ float rq[8], rd[8], rg[8];
    __shared__ int   rp_[8];
    const int warp = threadIdx.x >> 5;
    const int lane = threadIdx.x & 31;
    if (lane == 0) { rq[warp] = qfl; rd[warp] = dfl; rg[warp] = giou_l; rp_[warp] = posi; }
    __syncthreads();
    if (threadIdx.x == 0) {
        float q = 0.f, dd = 0.f, gg = 0.f; int pp = 0;
#pragma unroll
        for (int wi = 0; wi < LOSS_BLK / 32; wi++) {
            q += rq[wi]; dd += rd[wi]; gg += rg[wi]; pp += rp_[wi];
        }
        if (q  != 0.f) atomicAdd(&g_qfl,  (double)q);
        if (dd != 0.f) atomicAdd(&g_dfl,  (double)dd);
        if (gg != 0.f) atomicAdd(&g_giou, (double)gg);
        if (pp != 0)   atomicAdd(&g_pos,  pp);
        __threadfence();
        const unsigned int ticket = atomicAdd(&g_count, 1u);
        if (ticket == NBLOCKS - 1) {
            const int pos = *((volatile int*)&g_pos);
            const double sq = *((volatile double*)&g_qfl);
            const double sd = *((volatile double*)&g_dfl);
            const double sg = *((volatile double*)&g_giou);
            const double npc = (double)max(pos, 1);
            const double qv = sq / npc;
            double df = sd / (double)max(4 * pos, 1);
            df = fmin(fmax(df, 0.0), 1.0);
            const double gi = sg / npc;
            out[0] = (float)(qv + df + gi);
            out[1] = (float)qv;
            out[2] = (float)df;
            out[3] = (float)gi;
            g_qfl = 0.0; g_dfl = 0.0; g_giou = 0.0; g_pos = 0;
            __threadfence();
            g_count = 0u;
        }
    }
}

extern "C" void kernel_launch(void* const* d_in, const int* in_sizes, int n_in,
                              void* d_out, int out_size) {
    const float*  cls_preds = (const float*)d_in[0];
    const float*  reg_preds = (const float*)d_in[1];
    const float4* anchors   = (const float4*)d_in[2];
    const float4* gt_boxes  = (const float4*)d_in[3];
    const int*    gt_labels = (const int*)d_in[4];
    float* out = (float*)d_out;

    match_kernel<<<128, 128>>>(gt_boxes);
    dim3 grid(LOSS_GX, BATCH);
    loss_kernel<<<grid, LOSS_BLK>>>(cls_preds, reg_preds, anchors, gt_boxes, gt_labels, out);
}